// round 4
// baseline (speedup 1.0000x reference)
#include <cuda_runtime.h>
#include <math.h>
#include <stdint.h>

#define BB 64
#define TT 512
#define DD 256
#define HSZ 256
#define G4 1024
#define HS2 512
#define PITCH 260

// ---------------- device scratch (static: no allocation) ----------------
__device__ float g_XW[(size_t)TT * BB * G4];  // [t][b][gatecol]  128MB
__device__ float g_preH[BB * HSZ];
__device__ float g_preC[BB * HSZ];
__device__ float g_h[BB * HSZ];
__device__ float g_c[BB * HSZ];
__device__ unsigned g_bar[8];

// output offsets (floats)
#define OFF_HSEQ ((size_t)0)
#define OFF_CSEQ ((size_t)8388608)
#define OFF_HMU  ((size_t)16777216)
#define OFF_HSTD ((size_t)25165824)
#define OFF_CMU  ((size_t)33554432)
#define OFF_CSTD ((size_t)41943040)
#define OFF_HT   ((size_t)50331648)
#define OFF_CT   ((size_t)50348032)

// ---------------- f32x2 helpers ----------------
__device__ __forceinline__ void f2fma(unsigned long long& d, unsigned long long a,
                                      unsigned long long b) {
    asm("fma.rn.f32x2 %0, %1, %2, %0;" : "+l"(d) : "l"(a), "l"(b));
}
__device__ __forceinline__ float f2sum(unsigned long long v) {
    float lo, hi;
    asm("mov.b64 {%0,%1}, %2;" : "=f"(lo), "=f"(hi) : "l"(v));
    return lo + hi;
}

__global__ void bar_reset_kernel() {
    if (threadIdx.x < 8) g_bar[threadIdx.x] = 0u;
}

// ---------------- precompute: XW[t][b][col] = x[b][t][:] @ W_ih + bias ----------------
// k-paired SMEM layouts for f32x2 accumulation.
#define XSP_STRIDE 140
#define WSP_STRIDE 132

__global__ __launch_bounds__(256) void xw_kernel(const float* __restrict__ x,
                                                 const float* __restrict__ wih,
                                                 const float* __restrict__ bias) {
    __shared__ float XsP[32 * XSP_STRIDE];  // [k2][t*2+par]
    __shared__ float WsP[32 * WSP_STRIDE];  // [k2][col*2+par]
    const int bx = blockIdx.x;      // 0..15  col block (64 cols)
    const int by = blockIdx.y;      // 0..7   t block (64 t)
    const int bz = blockIdx.z;      // 0..63  b
    const int tid = threadIdx.x;
    const int tx = tid & 15;        // col quad
    const int ty = tid >> 4;        // t quad

    unsigned long long acc[4][4];
#pragma unroll
    for (int i = 0; i < 4; i++)
#pragma unroll
        for (int j = 0; j < 4; j++) acc[i][j] = 0ull;

    for (int kc = 0; kc < 4; kc++) {
        const int k0 = kc * 64;
        __syncthreads();
        for (int i = tid; i < 4096; i += 256) {
            int kk = i >> 6, cc = i & 63;
            WsP[(kk >> 1) * WSP_STRIDE + cc * 2 + (kk & 1)] =
                wih[(size_t)(k0 + kk) * G4 + bx * 64 + cc];
        }
        for (int i = tid; i < 4096; i += 256) {
            int tt2 = i >> 6, kk = i & 63;
            XsP[(kk >> 1) * XSP_STRIDE + tt2 * 2 + (kk & 1)] =
                x[((size_t)bz * TT + by * 64 + tt2) * DD + k0 + kk];
        }
        __syncthreads();
#pragma unroll 8
        for (int kk2 = 0; kk2 < 32; kk2++) {
            const float* XP = &XsP[kk2 * XSP_STRIDE + ty * 8];
            const float* WP = &WsP[kk2 * WSP_STRIDE + tx * 8];
            ulonglong2 aA = *(const ulonglong2*)XP;        // k-pairs for t0,t1
            ulonglong2 aB = *(const ulonglong2*)(XP + 4);  // t2,t3
            ulonglong2 wA = *(const ulonglong2*)WP;        // c0,c1
            ulonglong2 wB = *(const ulonglong2*)(WP + 4);  // c2,c3
            f2fma(acc[0][0], aA.x, wA.x); f2fma(acc[0][1], aA.x, wA.y);
            f2fma(acc[0][2], aA.x, wB.x); f2fma(acc[0][3], aA.x, wB.y);
            f2fma(acc[1][0], aA.y, wA.x); f2fma(acc[1][1], aA.y, wA.y);
            f2fma(acc[1][2], aA.y, wB.x); f2fma(acc[1][3], aA.y, wB.y);
            f2fma(acc[2][0], aB.x, wA.x); f2fma(acc[2][1], aB.x, wA.y);
            f2fma(acc[2][2], aB.x, wB.x); f2fma(acc[2][3], aB.x, wB.y);
            f2fma(acc[3][0], aB.y, wA.x); f2fma(acc[3][1], aB.y, wA.y);
            f2fma(acc[3][2], aB.y, wB.x); f2fma(acc[3][3], aB.y, wB.y);
        }
    }
    const int col0 = bx * 64 + tx * 4;
    const float4 bv = *(const float4*)&bias[col0];
#pragma unroll
    for (int i = 0; i < 4; i++) {
        int t = by * 64 + ty * 4 + i;
        float4 v;
        v.x = f2sum(acc[i][0]) + bv.x;
        v.y = f2sum(acc[i][1]) + bv.y;
        v.z = f2sum(acc[i][2]) + bv.z;
        v.w = f2sum(acc[i][3]) + bv.w;
        *(float4*)&g_XW[((size_t)t * BB + bz) * G4 + col0] = v;
    }
}

// ---------------- persistent recurrent kernel ----------------
__device__ __forceinline__ float ftanh_(float x) {
    float e = __expf(-2.f * fabsf(x));
    float t = __fdividef(1.f - e, 1.f + e);  // denom in [1,2]: safe
    return copysignf(t, x);
}
__device__ __forceinline__ float fsig_(float x) {
    return fmaf(0.5f, ftanh_(0.5f * x), 0.5f);
}

__device__ __forceinline__ void rg_barrier(unsigned* bar, unsigned target) {
    __syncthreads();
    if (threadIdx.x == 0) {
        asm volatile("red.release.gpu.add.u32 [%0], 1;" :: "l"(bar) : "memory");
        unsigned v;
        do {
            asm volatile("ld.acquire.gpu.u32 %0, [%1];" : "=r"(v) : "l"(bar) : "memory");
        } while (v < target);
    }
    __syncthreads();
}

#define SMEM_FLOATS (2 * 64 * PITCH + 3 * 8 * PITCH + 2 * 512)
#define SMEM_BYTES (SMEM_FLOATS * 4)

__global__ __launch_bounds__(256, 1) void lstm_kernel(const float* __restrict__ whh,
                                                      const float* __restrict__ hrep,
                                                      const float* __restrict__ crep,
                                                      const float* __restrict__ eps_h,
                                                      const float* __restrict__ eps_c,
                                                      float* __restrict__ out) {
    extern __shared__ float smem[];
    float* WaT = smem;                    // [64][PITCH]  gate-weight slice (transposed)
    float* WbT = WaT + 64 * PITCH;        // [64][PITCH]  reparam-weight slice (transposed)
    float* Hs  = WbT + 64 * PITCH;        // [8][PITCH]
    float* PH  = Hs + 8 * PITCH;          // [8][PITCH]
    float* PC  = PH + 8 * PITCH;          // [8][PITCH]
    float* Gs  = PC + 8 * PITCH;          // [64][8]
    float* Ps  = Gs + 512;                // [64][8]

    const int tid = threadIdx.x;
    const int rg = blockIdx.x >> 4;       // row group: rows rg*8 .. rg*8+7
    const int cb = blockIdx.x & 15;       // col block: j in [cb*16, cb*16+16)
    unsigned* bar = &g_bar[rg];

    // ---- one-time weight load into SMEM ----
    for (int i = tid; i < 64 * 256; i += 256) {
        int c = i & 63, k = i >> 6;
        int gcol = (c >> 4) * 256 + cb * 16 + (c & 15);
        WaT[c * PITCH + k] = whh[(size_t)k * G4 + gcol];
        int mm = c >> 5, hf = (c >> 4) & 1, jj = c & 15;
        int col2 = hf * 256 + cb * 16 + jj;
        WbT[c * PITCH + k] = (mm ? crep : hrep)[(size_t)k * HS2 + col2];
    }
    __syncthreads();

    // GEMM thread mapping
    const int c = tid >> 2;               // 0..63 (column within slice)
    const int rh = tid & 3;               // rows rh, rh+4
    const int gcol = (c >> 4) * 256 + cb * 16 + (c & 15);
    const int mb = c >> 5;                // phase-B matrix select
    // nonlinearity thread mapping (tid < 128)
    const int nr = tid >> 4;              // valid when tid < 128
    const int njj = tid & 15;
    const int nb = rg * 8 + (nr & 7), nj = cb * 16 + njj;
    // sampling thread mapping
    const int smm = tid >> 7, srow = (tid >> 4) & 7, sjj = tid & 15;
    const int sb = rg * 8 + srow, sj = cb * 16 + sjj;
    const float* epsp = smm ? eps_c : eps_h;
    const size_t off_seq = smm ? OFF_CSEQ : OFF_HSEQ;
    const size_t off_mu  = smm ? OFF_CMU  : OFF_HMU;
    const size_t off_std = smm ? OFF_CSTD : OFF_HSTD;
    const size_t off_fin = smm ? OFF_CT   : OFF_HT;
    float* statep = smm ? g_c : g_h;

    unsigned target = 0;

    for (int t = 0; t < TT; t++) {
        // ---- early prefetches: XW(t), c_old(t), eps(t) (hide L2/DRAM latency) ----
        const int base = (t * BB + rg * 8 + rh) * G4 + gcol;
        float a0 = __ldcg(&g_XW[base]);
        float a1 = __ldcg(&g_XW[base + 4 * G4]);
        float cold = 0.f;
        if (tid < 128 && t > 0) cold = __ldcg(&g_c[nb * HSZ + nj]);
        float ep = __ldg(&epsp[((size_t)t * BB + sb) * HSZ + sj]);

        // ---- stage h rows (float4) ----
        if (t == 0) {
            float4 z = make_float4(0.f, 0.f, 0.f, 0.f);
            for (int i = tid; i < 512; i += 256) {
                int r = i >> 6, k4 = (i & 63) << 2;
                *(float4*)&Hs[r * PITCH + k4] = z;
            }
        } else {
            for (int i = tid; i < 512; i += 256) {
                int r = i >> 6, k4 = (i & 63) << 2;
                *(float4*)&Hs[r * PITCH + k4] =
                    __ldcg((const float4*)&g_h[(rg * 8 + r) * HSZ + k4]);
            }
        }
        __syncthreads();

        // ---- phase A: gates tile = XW[t] + h @ W_hh (f32x2) ----
        {
            const ulonglong2* wv = (const ulonglong2*)&WaT[c * PITCH];
            const ulonglong2* ha = (const ulonglong2*)&Hs[rh * PITCH];
            const ulonglong2* hb = (const ulonglong2*)&Hs[(rh + 4) * PITCH];
            unsigned long long p0 = 0ull, p1 = 0ull, q0 = 0ull, q1 = 0ull;
#pragma unroll 8
            for (int i = 0; i < 64; i++) {
                ulonglong2 w = wv[i];
                ulonglong2 u = ha[i];
                ulonglong2 v = hb[i];
                f2fma(p0, u.x, w.x); f2fma(p1, u.y, w.y);
                f2fma(q0, v.x, w.x); f2fma(q1, v.y, w.y);
            }
            Gs[c * 8 + rh] = a0 + f2sum(p0) + f2sum(p1);
            Gs[c * 8 + rh + 4] = a1 + f2sum(q0) + f2sum(q1);
        }
        __syncthreads();

        // ---- nonlinearity -> pre_c, pre_h ----
        if (tid < 128) {
            int r = nr, jj = njj;
            float vi = fsig_(Gs[((0 << 4) | jj) * 8 + r]);
            float vf = fsig_(Gs[((1 << 4) | jj) * 8 + r]);
            float vg = ftanh_(Gs[((2 << 4) | jj) * 8 + r]);
            float vo = fsig_(Gs[((3 << 4) | jj) * 8 + r]);
            float pc = vf * cold + vi * vg;
            float ph = vo * ftanh_(cold);
            __stcg(&g_preC[nb * HSZ + nj], pc);
            __stcg(&g_preH[nb * HSZ + nj], ph);
        }
        target += 16;
        rg_barrier(bar, target);

        // ---- stage pre rows (float4) ----
        for (int i = tid; i < 1024; i += 256) {
            int m = i >> 9, r = (i >> 6) & 7, k4 = (i & 63) << 2;
            float* dst = m ? PC : PH;
            const float* src = m ? g_preC : g_preH;
            *(float4*)&dst[r * PITCH + k4] =
                __ldcg((const float4*)&src[(rg * 8 + r) * HSZ + k4]);
        }
        __syncthreads();

        // ---- phase B: reparam GEMM (f32x2) ----
        {
            const float* srcm = mb ? PC : PH;
            const ulonglong2* wv = (const ulonglong2*)&WbT[c * PITCH];
            const ulonglong2* ha = (const ulonglong2*)&srcm[rh * PITCH];
            const ulonglong2* hb = (const ulonglong2*)&srcm[(rh + 4) * PITCH];
            unsigned long long p0 = 0ull, p1 = 0ull, q0 = 0ull, q1 = 0ull;
#pragma unroll 8
            for (int i = 0; i < 64; i++) {
                ulonglong2 w = wv[i];
                ulonglong2 u = ha[i];
                ulonglong2 v = hb[i];
                f2fma(p0, u.x, w.x); f2fma(p1, u.y, w.y);
                f2fma(q0, v.x, w.x); f2fma(q1, v.y, w.y);
            }
            Ps[c * 8 + rh] = f2sum(p0) + f2sum(p1);
            Ps[c * 8 + rh + 4] = f2sum(q0) + f2sum(q1);
        }
        __syncthreads();

        // ---- sample + write outputs + update state ----
        {
            float mu = Ps[((smm << 5) | sjj) * 8 + srow];
            float sr = Ps[((smm << 5) | 16 | sjj) * 8 + srow];
            mu = fminf(fmaxf(mu, 1e-6f), 1e6f);
            float sp = fmaxf(sr, 0.f) + log1pf(__expf(-fabsf(sr)));
            float sd = fmaxf(sp, 1e-6f);
            float val = fmaf(ep, sd, mu);
            __stcg(&statep[sb * HSZ + sj], val);
            size_t o = (size_t)sb * (TT * HSZ) + (size_t)t * HSZ + sj;
            out[off_seq + o] = val;
            out[off_mu + o] = mu;
            out[off_std + o] = sd;
            if (t == TT - 1) out[off_fin + sb * HSZ + sj] = val;
        }
        target += 16;
        rg_barrier(bar, target);
    }
}

// ---------------- launch ----------------
extern "C" void kernel_launch(void* const* d_in, const int* in_sizes, int n_in,
                              void* d_out, int out_size) {
    (void)in_sizes; (void)n_in; (void)out_size;
    const float* x     = (const float*)d_in[0];
    const float* wih   = (const float*)d_in[1];
    const float* whh   = (const float*)d_in[2];
    const float* bias  = (const float*)d_in[3];
    const float* hrep  = (const float*)d_in[4];
    const float* crep  = (const float*)d_in[5];
    const float* eps_h = (const float*)d_in[6];
    const float* eps_c = (const float*)d_in[7];
    float* out = (float*)d_out;

    cudaFuncSetAttribute(lstm_kernel, cudaFuncAttributeMaxDynamicSharedMemorySize, SMEM_BYTES);

    bar_reset_kernel<<<1, 32>>>();
    xw_kernel<<<dim3(16, 8, 64), 256>>>(x, wih, bias);
    lstm_kernel<<<128, 256, SMEM_BYTES>>>(whh, hrep, crep, eps_h, eps_c, out);
}

// round 6
// speedup vs baseline: 1.1988x; 1.1988x over previous
#include <cuda_runtime.h>
#include <math.h>
#include <stdint.h>

#define BB 64
#define TT 512
#define DD 256
#define HSZ 256
#define G4 1024
#define HS2 512

typedef unsigned long long ull;

// ---------------- device scratch (static: no allocation) ----------------
__device__ float g_XW[(size_t)TT * BB * G4];  // [t][b][gatecol]  128MB
__device__ float g_preH[BB * HSZ];
__device__ float g_preC[BB * HSZ];
__device__ float g_h[BB * HSZ];
__device__ unsigned g_bar[8];

// output offsets (floats)
#define OFF_HSEQ ((size_t)0)
#define OFF_CSEQ ((size_t)8388608)
#define OFF_HMU  ((size_t)16777216)
#define OFF_HSTD ((size_t)25165824)
#define OFF_CMU  ((size_t)33554432)
#define OFF_CSTD ((size_t)41943040)
#define OFF_HT   ((size_t)50331648)
#define OFF_CT   ((size_t)50348032)

// ---------------- f32x2 helpers ----------------
__device__ __forceinline__ void f2fma(ull& d, ull a, ull b) {
    asm("fma.rn.f32x2 %0, %1, %2, %0;" : "+l"(d) : "l"(a), "l"(b));
}
__device__ __forceinline__ float f2sum(ull v) {
    float lo, hi;
    asm("mov.b64 {%0,%1}, %2;" : "=f"(lo), "=f"(hi) : "l"(v));
    return lo + hi;
}
__device__ __forceinline__ ull f2pack(float lo, float hi) {
    ull v;
    asm("mov.b64 %0, {%1,%2};" : "=l"(v) : "f"(lo), "f"(hi));
    return v;
}
// 16B global load (L2, coherent across SMs) straight into two b64 regs
__device__ __forceinline__ void ld16cg(const float* p, ull& lo, ull& hi) {
    asm volatile("ld.global.cg.v2.b64 {%0,%1}, [%2];" : "=l"(lo), "=l"(hi) : "l"(p));
}

__global__ void bar_reset_kernel() {
    if (threadIdx.x < 8) g_bar[threadIdx.x] = 0u;
}

// ---------------- precompute: XW[t][b][col] = x[b][t][:] @ W_ih + bias ----------------
#define XSP_STRIDE 140
#define WSP_STRIDE 132

__global__ __launch_bounds__(256) void xw_kernel(const float* __restrict__ x,
                                                 const float* __restrict__ wih,
                                                 const float* __restrict__ bias) {
    __shared__ float XsP[32 * XSP_STRIDE];  // [k2][t*2+par]
    __shared__ float WsP[32 * WSP_STRIDE];  // [k2][col*2+par]
    const int bx = blockIdx.x;      // 0..15  col block (64 cols)
    const int by = blockIdx.y;      // 0..7   t block (64 t)
    const int bz = blockIdx.z;      // 0..63  b
    const int tid = threadIdx.x;
    const int tx = tid & 15;        // col quad
    const int ty = tid >> 4;        // t quad

    ull acc[4][4];
#pragma unroll
    for (int i = 0; i < 4; i++)
#pragma unroll
        for (int j = 0; j < 4; j++) acc[i][j] = 0ull;

    for (int kc = 0; kc < 4; kc++) {
        const int k0 = kc * 64;
        __syncthreads();
        for (int i = tid; i < 4096; i += 256) {
            int kk = i >> 6, cc = i & 63;
            WsP[(kk >> 1) * WSP_STRIDE + cc * 2 + (kk & 1)] =
                wih[(size_t)(k0 + kk) * G4 + bx * 64 + cc];
        }
        for (int i = tid; i < 4096; i += 256) {
            int tt2 = i >> 6, kk = i & 63;
            XsP[(kk >> 1) * XSP_STRIDE + tt2 * 2 + (kk & 1)] =
                x[((size_t)bz * TT + by * 64 + tt2) * DD + k0 + kk];
        }
        __syncthreads();
#pragma unroll 8
        for (int kk2 = 0; kk2 < 32; kk2++) {
            const float* XP = &XsP[kk2 * XSP_STRIDE + ty * 8];
            const float* WP = &WsP[kk2 * WSP_STRIDE + tx * 8];
            ulonglong2 aA = *(const ulonglong2*)XP;
            ulonglong2 aB = *(const ulonglong2*)(XP + 4);
            ulonglong2 wA = *(const ulonglong2*)WP;
            ulonglong2 wB = *(const ulonglong2*)(WP + 4);
            f2fma(acc[0][0], aA.x, wA.x); f2fma(acc[0][1], aA.x, wA.y);
            f2fma(acc[0][2], aA.x, wB.x); f2fma(acc[0][3], aA.x, wB.y);
            f2fma(acc[1][0], aA.y, wA.x); f2fma(acc[1][1], aA.y, wA.y);
            f2fma(acc[1][2], aA.y, wB.x); f2fma(acc[1][3], aA.y, wB.y);
            f2fma(acc[2][0], aB.x, wA.x); f2fma(acc[2][1], aB.x, wA.y);
            f2fma(acc[2][2], aB.x, wB.x); f2fma(acc[2][3], aB.x, wB.y);
            f2fma(acc[3][0], aB.y, wA.x); f2fma(acc[3][1], aB.y, wA.y);
            f2fma(acc[3][2], aB.y, wB.x); f2fma(acc[3][3], aB.y, wB.y);
        }
    }
    const int col0 = bx * 64 + tx * 4;
    const float4 bv = *(const float4*)&bias[col0];
#pragma unroll
    for (int i = 0; i < 4; i++) {
        int t = by * 64 + ty * 4 + i;
        float4 v;
        v.x = f2sum(acc[i][0]) + bv.x;
        v.y = f2sum(acc[i][1]) + bv.y;
        v.z = f2sum(acc[i][2]) + bv.z;
        v.w = f2sum(acc[i][3]) + bv.w;
        *(float4*)&g_XW[((size_t)t * BB + bz) * G4 + col0] = v;
    }
}

// ---------------- fast nonlinearities ----------------
__device__ __forceinline__ float ftanh_(float x) {
    float e = __expf(-2.f * fabsf(x));
    float t = __fdividef(1.f - e, 1.f + e);
    return copysignf(t, x);
}
__device__ __forceinline__ float fsig_(float x) {
    return fmaf(0.5f, ftanh_(0.5f * x), 0.5f);
}

__device__ __forceinline__ void rg_barrier(unsigned* bar, unsigned target) {
    __syncthreads();
    if (threadIdx.x == 0) {
        asm volatile("red.release.gpu.add.u32 [%0], 1;" :: "l"(bar) : "memory");
        unsigned v;
        do {
            asm volatile("ld.acquire.gpu.u32 %0, [%1];" : "=r"(v) : "l"(bar) : "memory");
        } while (v < target);
    }
    __syncthreads();
}

// ---------------- persistent recurrent kernel (register-stationary weights) ----------------
#define PAD 68

__global__ __launch_bounds__(256, 1) void lstm_kernel(const float* __restrict__ whh,
                                                      const float* __restrict__ hrep,
                                                      const float* __restrict__ crep,
                                                      const float* __restrict__ eps_h,
                                                      const float* __restrict__ eps_c,
                                                      float* __restrict__ out) {
    __shared__ __align__(16) float Part[8 * 4 * PAD];  // [r][ks][cl] padded
    __shared__ float Cs[128];                          // c state, CTA-local [r][j]

    const int tid = threadIdx.x;
    const int rg = blockIdx.x >> 4;       // row group: rows rg*8 .. rg*8+7
    const int cb = blockIdx.x & 15;       // col block
    unsigned* bar = &g_bar[rg];
    const int w = tid >> 5, lane = tid & 31;
    const bool roleA = (w < 4);
    const int ks = roleA ? w : (w - 4);   // k-slice: k in [ks*64, ks*64+64)

    // ---- one-time weight load into REGISTERS (2 cols x 64 k, as k-pairs) ----
    ull wc0[32], wc1[32];
    int cl0;  // local output column base (even)
    if (roleA) {
        const int q = lane >> 3, jp = lane & 7;
        const int gc = q * 256 + cb * 16 + jp * 2;
        const float* wp = whh + (size_t)(ks * 64) * G4 + gc;
        cl0 = q * 16 + jp * 2;
#pragma unroll
        for (int i = 0; i < 32; i++) {
            float2 v0 = *(const float2*)(wp + (size_t)(2 * i) * G4);
            float2 v1 = *(const float2*)(wp + (size_t)(2 * i + 1) * G4);
            wc0[i] = f2pack(v0.x, v1.x);
            wc1[i] = f2pack(v0.y, v1.y);
        }
    } else {
        const int mm = lane >> 4, hf = (lane >> 3) & 1, jp = lane & 7;
        const float* M = mm ? crep : hrep;
        const int rc = hf * 256 + cb * 16 + jp * 2;
        const float* wp = M + (size_t)(ks * 64) * HS2 + rc;
        cl0 = mm * 32 + hf * 16 + jp * 2;
#pragma unroll
        for (int i = 0; i < 32; i++) {
            float2 v0 = *(const float2*)(wp + (size_t)(2 * i) * HS2);
            float2 v1 = *(const float2*)(wp + (size_t)(2 * i + 1) * HS2);
            wc0[i] = f2pack(v0.x, v1.x);
            wc1[i] = f2pack(v0.y, v1.y);
        }
    }

    // phase-B source: lanes 0-15 use preH (h reparam), 16-31 use preC (c reparam)
    const float* srcB = ((lane >> 4) ? g_preC : g_preH) + (size_t)(rg * 8) * HSZ + ks * 64;
    const float* srcA = g_h + (size_t)(rg * 8) * HSZ + ks * 64;

    // nonlinearity mapping (tid < 128)
    const int nj = tid & 15, nr = tid >> 4;
    // sampling mapping (all 256)
    const int smm = tid >> 7, srow = (tid >> 4) & 7, sjj = tid & 15;
    const int sb = rg * 8 + srow, sj = cb * 16 + sjj;
    const float* epsp = smm ? eps_c : eps_h;
    const size_t off_seq = smm ? OFF_CSEQ : OFF_HSEQ;
    const size_t off_mu  = smm ? OFF_CMU  : OFF_HMU;
    const size_t off_std = smm ? OFF_CSTD : OFF_HSTD;
    const size_t off_fin = smm ? OFF_CT   : OFF_HT;

    if (tid < 128) Cs[tid] = 0.f;
    __syncthreads();

    unsigned target = 0;

    for (int t = 0; t < TT; t++) {
        // ---- prefetch XW(t) for nonlin + eps(t) for sampling ----
        float xw0 = 0.f, xw1 = 0.f, xw2 = 0.f, xw3 = 0.f;
        if (tid < 128) {
            const float* xp = g_XW + (size_t)(t * BB + rg * 8 + nr) * G4 + cb * 16 + nj;
            xw0 = __ldcg(xp);
            xw1 = __ldcg(xp + 256);
            xw2 = __ldcg(xp + 512);
            xw3 = __ldcg(xp + 768);
        }
        const float ep = __ldg(&epsp[((size_t)t * BB + sb) * HSZ + sj]);

        // ---- phase A: partial gates = h @ W_hh slice (warps 0-3) ----
        if (roleA) {
            ull a0[8], a1[8];
#pragma unroll
            for (int r = 0; r < 8; r++) { a0[r] = 0ull; a1[r] = 0ull; }
            if (t) {
#pragma unroll
                for (int i = 0; i < 16; i++) {
                    ull hl[8], hh[8];
#pragma unroll
                    for (int r = 0; r < 8; r++) ld16cg(srcA + r * HSZ + i * 4, hl[r], hh[r]);
#pragma unroll
                    for (int r = 0; r < 8; r++) {
                        f2fma(a0[r], hl[r], wc0[2 * i]); f2fma(a0[r], hh[r], wc0[2 * i + 1]);
                        f2fma(a1[r], hl[r], wc1[2 * i]); f2fma(a1[r], hh[r], wc1[2 * i + 1]);
                    }
                }
            }
#pragma unroll
            for (int r = 0; r < 8; r++) {
                float2 v = make_float2(f2sum(a0[r]), f2sum(a1[r]));
                *(float2*)&Part[(r * 4 + ks) * PAD + cl0] = v;
            }
        }
        __syncthreads();

        // ---- nonlinearity -> pre_c, pre_h (exchange via L2) ----
        if (tid < 128) {
            float s0, s1, s2, s3;
            {
                int b0 = nr * 4 * PAD + nj;
                s0 = Part[b0] + Part[b0 + PAD] + Part[b0 + 2 * PAD] + Part[b0 + 3 * PAD];
                s1 = Part[b0 + 16] + Part[b0 + 16 + PAD] + Part[b0 + 16 + 2 * PAD] + Part[b0 + 16 + 3 * PAD];
                s2 = Part[b0 + 32] + Part[b0 + 32 + PAD] + Part[b0 + 32 + 2 * PAD] + Part[b0 + 32 + 3 * PAD];
                s3 = Part[b0 + 48] + Part[b0 + 48 + PAD] + Part[b0 + 48 + 2 * PAD] + Part[b0 + 48 + 3 * PAD];
            }
            float vi = fsig_(s0 + xw0);
            float vf = fsig_(s1 + xw1);
            float vg = ftanh_(s2 + xw2);
            float vo = fsig_(s3 + xw3);
            float cold = Cs[tid];
            float pc = vf * cold + vi * vg;
            float ph = vo * ftanh_(cold);
            int b = rg * 8 + nr, j = cb * 16 + nj;
            __stcg(&g_preC[b * HSZ + j], pc);
            __stcg(&g_preH[b * HSZ + j], ph);
        }
        target += 16;
        rg_barrier(bar, target);

        // ---- phase B: reparam partials (warps 4-7) ----
        if (!roleA) {
            ull a0[8], a1[8];
#pragma unroll
            for (int r = 0; r < 8; r++) { a0[r] = 0ull; a1[r] = 0ull; }
#pragma unroll
            for (int i = 0; i < 16; i++) {
                ull hl[8], hh[8];
#pragma unroll
                for (int r = 0; r < 8; r++) ld16cg(srcB + r * HSZ + i * 4, hl[r], hh[r]);
#pragma unroll
                for (int r = 0; r < 8; r++) {
                    f2fma(a0[r], hl[r], wc0[2 * i]); f2fma(a0[r], hh[r], wc0[2 * i + 1]);
                    f2fma(a1[r], hl[r], wc1[2 * i]); f2fma(a1[r], hh[r], wc1[2 * i + 1]);
                }
            }
#pragma unroll
            for (int r = 0; r < 8; r++) {
                float2 v = make_float2(f2sum(a0[r]), f2sum(a1[r]));
                *(float2*)&Part[(r * 4 + ks) * PAD + cl0] = v;
            }
        }
        __syncthreads();

        // ---- sample + write outputs + update state ----
        {
            int b0 = srow * 4 * PAD + smm * 32 + sjj;
            float mu = Part[b0] + Part[b0 + PAD] + Part[b0 + 2 * PAD] + Part[b0 + 3 * PAD];
            float sr = Part[b0 + 16] + Part[b0 + 16 + PAD] + Part[b0 + 16 + 2 * PAD] + Part[b0 + 16 + 3 * PAD];
            mu = fminf(fmaxf(mu, 1e-6f), 1e6f);
            float sp = fmaxf(sr, 0.f) + log1pf(__expf(-fabsf(sr)));
            float sd = fmaxf(sp, 1e-6f);
            float val = fmaf(ep, sd, mu);
            if (smm) Cs[srow * 16 + sjj] = val;            // c state stays CTA-local
            else __stcg(&g_h[sb * HSZ + sj], val);         // h must cross CTAs
            size_t o = (size_t)sb * (TT * HSZ) + (size_t)t * HSZ + sj;
            out[off_seq + o] = val;
            out[off_mu + o] = mu;
            out[off_std + o] = sd;
            if (t == TT - 1) out[off_fin + sb * HSZ + sj] = val;
        }
        target += 16;
        rg_barrier(bar, target);
    }
}

// ---------------- launch ----------------
extern "C" void kernel_launch(void* const* d_in, const int* in_sizes, int n_in,
                              void* d_out, int out_size) {
    (void)in_sizes; (void)n_in; (void)out_size;
    const float* x     = (const float*)d_in[0];
    const float* wih   = (const float*)d_in[1];
    const float* whh   = (const float*)d_in[2];
    const float* bias  = (const float*)d_in[3];
    const float* hrep  = (const float*)d_in[4];
    const float* crep  = (const float*)d_in[5];
    const float* eps_h = (const float*)d_in[6];
    const float* eps_c = (const float*)d_in[7];
    float* out = (float*)d_out;

    bar_reset_kernel<<<1, 32>>>();
    xw_kernel<<<dim3(16, 8, 64), 256>>>(x, wih, bias);
    lstm_kernel<<<128, 256>>>(whh, hrep, crep, eps_h, eps_c, out);
}